// round 14
// baseline (speedup 1.0000x reference)
#include <cuda_runtime.h>
#include <cuda_bf16.h>
#include <cstdint>

#define N_NODES 100000
#define N_RELS  200
#define D       200
#define BN_EPS  1e-5f

#define SEGW 208          // per-segment padded K (200 real + 8 zero)
#define KCAT 624          // 3 * SEGW
#define NCHUNK 39         // 39 chunks of K=16
#define NPAD 224          // padded N for the GEMM (200 real)
#define N_TILES 782       // ceil(100000/128)

// ---------------- scratch (no cudaMalloc allowed) ----------------
__device__ float g_A[2][(size_t)N_NODES * D];   // in / out edge accumulators
__device__ float g_sum[D];
__device__ float g_sq[D];
__device__ __nv_bfloat16 g_Bhi[200 * KCAT];     // weights, split-bf16, K-major [n][kcat]
__device__ __nv_bfloat16 g_Blo[200 * KCAT];

// ---------------- PTX helpers (base ISA only — no sm_103a features!) ----------------
__device__ __forceinline__ uint32_t smem_u32(const void* p) {
    uint32_t a;
    asm("{ .reg .u64 t; cvta.to.shared.u64 t, %1; cvt.u32.u64 %0, t; }" : "=r"(a) : "l"(p));
    return a;
}

#define LDSM4(r, addr) \
    asm volatile("ldmatrix.sync.aligned.m8n8.x4.shared.b16 {%0,%1,%2,%3}, [%4];" \
                 : "=r"((r)[0]), "=r"((r)[1]), "=r"((r)[2]), "=r"((r)[3]) : "r"(addr))
#define LDSM2(r, addr) \
    asm volatile("ldmatrix.sync.aligned.m8n8.x2.shared.b16 {%0,%1}, [%2];" \
                 : "=r"((r)[0]), "=r"((r)[1]) : "r"(addr))

#define MMA16816(d, a, b0, b1) \
    asm volatile("mma.sync.aligned.m16n8k16.row.col.f32.bf16.bf16.f32 " \
                 "{%0,%1,%2,%3}, {%4,%5,%6,%7}, {%8,%9}, {%0,%1,%2,%3};" \
                 : "+f"((d)[0]), "+f"((d)[1]), "+f"((d)[2]), "+f"((d)[3]) \
                 : "r"((a)[0]), "r"((a)[1]), "r"((a)[2]), "r"((a)[3]), "r"(b0), "r"(b1))

#define REDV4(p, a, b, c, dd) \
    asm volatile("red.global.add.v4.f32 [%0], {%1,%2,%3,%4};" \
                 :: "l"(p), "f"(a), "f"(b), "f"(c), "f"(dd) : "memory")

// ---------------- zero scratch ----------------
__global__ void k_zero() {
    float4* p = (float4*)&g_A[0][0];
    size_t n4 = (size_t)2 * N_NODES * D / 4;
    size_t stride = (size_t)gridDim.x * blockDim.x;
    for (size_t i = (size_t)blockIdx.x * blockDim.x + threadIdx.x; i < n4; i += stride)
        p[i] = make_float4(0.f, 0.f, 0.f, 0.f);
    if (blockIdx.x == 0 && threadIdx.x < D) {
        g_sum[threadIdx.x] = 0.f;
        g_sq[threadIdx.x]  = 0.f;
    }
}

// ---------------- edge scatter: vector red.global.add.v4 ----------------
__global__ void k_scatter(const float* __restrict__ x,
                          const float* __restrict__ rel,
                          const float* __restrict__ enorm,
                          const int*  __restrict__ esrc,
                          const int*  __restrict__ edst,
                          const int*  __restrict__ etyp,
                          int E, int half) {
    int w    = (blockIdx.x * blockDim.x + threadIdx.x) >> 5;
    int lane = threadIdx.x & 31;
    if (w >= E) return;
    int s = esrc[w];
    int d = edst[w];
    int t = etyp[w];
    float c = enorm[w] * (1.f / 3.f);
    const float4* xr = (const float4*)(x   + (size_t)s * D);
    const float4* rr = (const float4*)(rel + (size_t)t * D);
    float* a = (w < half ? g_A[0] : g_A[1]) + (size_t)d * D;
    #pragma unroll
    for (int i = lane; i < D / 4; i += 32) {
        float4 xv = xr[i];
        float4 rv = rr[i];
        REDV4(a + 4 * i, xv.x * rv.x * c, xv.y * rv.y * c,
                          xv.z * rv.z * c, xv.w * rv.w * c);
    }
}

// ---------------- fused: weight prep (blocks 0..199) + rel_out GEMM (blocks 200..399) ----------------
__global__ void k_prep_rel(const float* __restrict__ in_w,
                           const float* __restrict__ out_w,
                           const float* __restrict__ loop_w,
                           const float* __restrict__ loop_rel,
                           const float* __restrict__ rel,
                           const float* __restrict__ w_rel,
                           float* __restrict__ relout) {
    if (blockIdx.x < 200) {
        int n    = blockIdx.x;       // 0..199
        int kcat = threadIdx.x;      // 0..623
        int seg  = kcat / SEGW;
        int k    = kcat - seg * SEGW;
        float v = 0.f;
        if (k < D) {
            const float* W = (seg == 0) ? in_w : (seg == 1) ? out_w : loop_w;
            v = W[k * D + n];
            if (seg == 2) v *= loop_rel[k] * (1.f / 3.f);
        }
        __nv_bfloat16 hi = __float2bfloat16(v);
        float lo = v - __bfloat162float(hi);
        g_Bhi[n * KCAT + kcat] = hi;
        g_Blo[n * KCAT + kcat] = __float2bfloat16(lo);
    } else {
        int i = blockIdx.x - 200;    // rel row
        int j = threadIdx.x;         // col
        if (j < D) {
            float s = 0.f;
            #pragma unroll 4
            for (int k = 0; k < D; k++)
                s = fmaf(rel[i * D + k], w_rel[k * D + j], s);
            relout[i * D + j] = s;
        }
    }
}

// ---------------- node GEMM on HMMA: double-buffered, fused BN stats, 2 CTAs/SM ----------------
// h[128 x 200] = [A_in | A_out | x] @ Bsplit   per CTA tile.
// 512 threads = 16 warps in 4x4 grid; warp tile 32 rows x 56 cols (2 m16 x 7 n8).
#define A_STRIDE 48       // bytes per A row (16 bf16 padded to 24)
#define B_STRIDE 48
#define A_HI_OFF 0
#define A_LO_OFF 6144     // 128*48
#define B_HI_OFF 12288
#define B_LO_OFF 23040    // 12288 + 224*48
#define BUF_SZ   33792    // 23040 + 224*48
#define STAT_OFF (2 * BUF_SZ)          // s_sum[200], s_sq[200]
#define SMEM_DYN (2 * BUF_SZ + 2 * 200 * 4)   // 69184

__global__ __launch_bounds__(512, 2)
void k_gemm(const float* __restrict__ x, float* __restrict__ h) {
    extern __shared__ __align__(16) char smem[];
    const int tid  = threadIdx.x;
    const int wid  = tid >> 5;
    const int lane = tid & 31;
    const int wr   = wid >> 2;          // warp row group 0..3
    const int wc   = wid & 3;           // warp col group 0..3
    const int row0 = blockIdx.x * 128;

    const uint32_t uBase = smem_u32(smem);
    float* s_sum = (float*)(smem + STAT_OFF);
    float* s_sq  = s_sum + 200;
    if (tid < 200) { s_sum[tid] = 0.f; s_sq[tid] = 0.f; }

    // ldmatrix lane offsets
    const uint32_t aOff = (uint32_t)(lane & 15) * A_STRIDE + (uint32_t)(lane >> 4) * 16;
    const uint32_t bOff4 = ((uint32_t)(((lane >> 4) << 3) + (lane & 7))) * B_STRIDE +
                           (uint32_t)((lane >> 3) & 1) * 16;
    const uint32_t bOff2 = (uint32_t)(lane & 7) * B_STRIDE + (uint32_t)((lane >> 3) & 1) * 16;

    const float* Asrc[3] = { g_A[0], g_A[1], x };

    float acc[2][7][4];
    #pragma unroll
    for (int m = 0; m < 2; m++)
        #pragma unroll
        for (int n = 0; n < 7; n++)
            #pragma unroll
            for (int q = 0; q < 4; q++) acc[m][n][q] = 0.f;

    // prefetch task mapping
    const int prow = tid >> 2;          // A row
    const int pkg  = tid & 3;           // A k-group (4 floats)
    float4 a_pf;
    uint4  b_pf0, b_pf1;

    auto prefetch = [&](int seg, int kb) {
        const float* Ap = Asrc[seg];
        bool av = (row0 + prow < N_NODES) && (kb + pkg * 4 < D);
        a_pf = av ? *(const float4*)(Ap + (size_t)(row0 + prow) * D + kb + pkg * 4)
                  : make_float4(0.f, 0.f, 0.f, 0.f);
        int kcat = seg * SEGW + kb;
        {
            int t0 = tid;
            int pl = t0 / 448, rem = t0 - pl * 448, rw = rem >> 1, hf = rem & 1;
            const __nv_bfloat16* src = pl ? g_Blo : g_Bhi;
            b_pf0 = (rw < 200) ? *(const uint4*)(src + rw * KCAT + kcat + hf * 8)
                               : make_uint4(0, 0, 0, 0);
        }
        if (tid < 384) {
            int t1 = tid + 512;
            int pl = t1 / 448, rem = t1 - pl * 448, rw = rem >> 1, hf = rem & 1;
            const __nv_bfloat16* src = pl ? g_Blo : g_Bhi;
            b_pf1 = (rw < 200) ? *(const uint4*)(src + rw * KCAT + kcat + hf * 8)
                               : make_uint4(0, 0, 0, 0);
        }
    };

    auto store = [&](int buf) {
        char* base = smem + buf * BUF_SZ;
        __nv_bfloat16 h0 = __float2bfloat16(a_pf.x);
        __nv_bfloat16 h1 = __float2bfloat16(a_pf.y);
        __nv_bfloat16 h2 = __float2bfloat16(a_pf.z);
        __nv_bfloat16 h3 = __float2bfloat16(a_pf.w);
        __nv_bfloat16 l0 = __float2bfloat16(a_pf.x - __bfloat162float(h0));
        __nv_bfloat16 l1 = __float2bfloat16(a_pf.y - __bfloat162float(h1));
        __nv_bfloat16 l2 = __float2bfloat16(a_pf.z - __bfloat162float(h2));
        __nv_bfloat16 l3 = __float2bfloat16(a_pf.w - __bfloat162float(h3));
        uint32_t hij = (uint32_t)__bfloat16_as_ushort(h0) | ((uint32_t)__bfloat16_as_ushort(h1) << 16);
        uint32_t hkl = (uint32_t)__bfloat16_as_ushort(h2) | ((uint32_t)__bfloat16_as_ushort(h3) << 16);
        uint32_t lij = (uint32_t)__bfloat16_as_ushort(l0) | ((uint32_t)__bfloat16_as_ushort(l1) << 16);
        uint32_t lkl = (uint32_t)__bfloat16_as_ushort(l2) | ((uint32_t)__bfloat16_as_ushort(l3) << 16);
        *(uint2*)(base + A_HI_OFF + prow * A_STRIDE + pkg * 8) = make_uint2(hij, hkl);
        *(uint2*)(base + A_LO_OFF + prow * A_STRIDE + pkg * 8) = make_uint2(lij, lkl);
        {
            int t0 = tid;
            int pl = t0 / 448, rem = t0 - pl * 448, rw = rem >> 1, hf = rem & 1;
            char* dst = base + (pl ? B_LO_OFF : B_HI_OFF);
            *(uint4*)(dst + rw * B_STRIDE + hf * 16) = b_pf0;
        }
        if (tid < 384) {
            int t1 = tid + 512;
            int pl = t1 / 448, rem = t1 - pl * 448, rw = rem >> 1, hf = rem & 1;
            char* dst = base + (pl ? B_LO_OFF : B_HI_OFF);
            *(uint4*)(dst + rw * B_STRIDE + hf * 16) = b_pf1;
        }
    };

    // ---- prologue ----
    prefetch(0, 0);
    store(0);
    __syncthreads();
    prefetch(0, 16);          // chunk 1 in flight

    int seg = 0, kb = 16;     // (seg,kb) of the chunk currently prefetched
    for (int c = 0; c < NCHUNK; c++) {
        const uint32_t buf = (uint32_t)(c & 1) * BUF_SZ;
        const uint32_t uAhi = uBase + buf + A_HI_OFF;
        const uint32_t uAlo = uBase + buf + A_LO_OFF;
        const uint32_t uBhi = uBase + buf + B_HI_OFF;
        const uint32_t uBlo = uBase + buf + B_LO_OFF;

        // ---- compute chunk c (MMA hides the in-flight LDG prefetch) ----
        uint32_t ah[2][4], al[2][4];
        #pragma unroll
        for (int mt = 0; mt < 2; mt++) {
            uint32_t rbase = (uint32_t)(wr * 32 + mt * 16) * A_STRIDE;
            LDSM4(ah[mt], uAhi + rbase + aOff);
            LDSM4(al[mt], uAlo + rbase + aOff);
        }
        #pragma unroll
        for (int np = 0; np < 3; np++) {
            uint32_t nbase = (uint32_t)(wc * 56 + np * 16) * B_STRIDE;
            uint32_t bh[4], bl[4];
            LDSM4(bh, uBhi + nbase + bOff4);
            LDSM4(bl, uBlo + nbase + bOff4);
            #pragma unroll
            for (int mt = 0; mt < 2; mt++) {
                MMA16816(acc[mt][2 * np],     ah[mt], bh[0], bh[1]);
                MMA16816(acc[mt][2 * np],     ah[mt], bl[0], bl[1]);
                MMA16816(acc[mt][2 * np],     al[mt], bh[0], bh[1]);
                MMA16816(acc[mt][2 * np + 1], ah[mt], bh[2], bh[3]);
                MMA16816(acc[mt][2 * np + 1], ah[mt], bl[2], bl[3]);
                MMA16816(acc[mt][2 * np + 1], al[mt], bh[2], bh[3]);
            }
        }
        {
            uint32_t nbase = (uint32_t)(wc * 56 + 48) * B_STRIDE;
            uint32_t bh[2], bl[2];
            LDSM2(bh, uBhi + nbase + bOff2);
            LDSM2(bl, uBlo + nbase + bOff2);
            #pragma unroll
            for (int mt = 0; mt < 2; mt++) {
                MMA16816(acc[mt][6], ah[mt], bh[0], bh[1]);
                MMA16816(acc[mt][6], ah[mt], bl[0], bl[1]);
                MMA16816(acc[mt][6], al[mt], bh[0], bh[1]);
            }
        }

        // ---- store prefetched chunk c+1 into alternate buffer, start LDG c+2 ----
        if (c + 1 < NCHUNK) {
            store((c + 1) & 1);
            kb += 16;
            if (kb == SEGW) { kb = 0; seg++; }
            if (c + 2 < NCHUNK) prefetch(seg, kb);
        }
        __syncthreads();
    }

    // ---- epilogue 1: write h ----
    #pragma unroll
    for (int mt = 0; mt < 2; mt++) {
        int rlo = row0 + wr * 32 + mt * 16 + (lane >> 2);
        int rhi = rlo + 8;
        #pragma unroll
        for (int nt = 0; nt < 7; nt++) {
            int col = wc * 56 + nt * 8 + 2 * (lane & 3);
            if (col < D) {
                if (rlo < N_NODES)
                    *(float2*)(h + (size_t)rlo * D + col) = make_float2(acc[mt][nt][0], acc[mt][nt][1]);
                if (rhi < N_NODES)
                    *(float2*)(h + (size_t)rhi * D + col) = make_float2(acc[mt][nt][2], acc[mt][nt][3]);
            }
        }
    }

    // ---- epilogue 2: fused BN stats (sum / sumsq per column) ----
    #pragma unroll
    for (int nt = 0; nt < 7; nt++) {
        float s0 = acc[0][nt][0] + acc[0][nt][2] + acc[1][nt][0] + acc[1][nt][2];
        float s1 = acc[0][nt][1] + acc[0][nt][3] + acc[1][nt][1] + acc[1][nt][3];
        float q0 = acc[0][nt][0]*acc[0][nt][0] + acc[0][nt][2]*acc[0][nt][2]
                 + acc[1][nt][0]*acc[1][nt][0] + acc[1][nt][2]*acc[1][nt][2];
        float q1 = acc[0][nt][1]*acc[0][nt][1] + acc[0][nt][3]*acc[0][nt][3]
                 + acc[1][nt][1]*acc[1][nt][1] + acc[1][nt][3]*acc[1][nt][3];
        #pragma unroll
        for (int m = 4; m <= 16; m <<= 1) {
            s0 += __shfl_xor_sync(0xffffffffu, s0, m);
            s1 += __shfl_xor_sync(0xffffffffu, s1, m);
            q0 += __shfl_xor_sync(0xffffffffu, q0, m);
            q1 += __shfl_xor_sync(0xffffffffu, q1, m);
        }
        if (lane < 4) {
            int col = wc * 56 + nt * 8 + 2 * lane;
            if (col < D) {
                atomicAdd(&s_sum[col],     s0);
                atomicAdd(&s_sq[col],      q0);
                atomicAdd(&s_sum[col + 1], s1);
                atomicAdd(&s_sq[col + 1],  q1);
            }
        }
    }
    __syncthreads();
    if (tid < D) {
        atomicAdd(&g_sum[tid], s_sum[tid]);
        atomicAdd(&g_sq[tid],  s_sq[tid]);
    }
}

// ---------------- BatchNorm normalize (in place, float4) ----------------
__global__ void k_norm(float* __restrict__ h,
                       const float* __restrict__ gamma,
                       const float* __restrict__ beta) {
    __shared__ float s_scale[D];
    __shared__ float s_shift[D];
    if (threadIdx.x < D) {
        const float invN = 1.f / (float)N_NODES;
        float mean = g_sum[threadIdx.x] * invN;
        float var  = g_sq[threadIdx.x] * invN - mean * mean;
        float inv  = rsqrtf(var + BN_EPS);
        float sc   = inv * gamma[threadIdx.x];
        s_scale[threadIdx.x] = sc;
        s_shift[threadIdx.x] = beta[threadIdx.x] - mean * sc;
    }
    __syncthreads();
    float4* h4 = (float4*)h;
    size_t n4 = (size_t)N_NODES * D / 4;
    size_t stride = (size_t)gridDim.x * blockDim.x;
    for (size_t i = (size_t)blockIdx.x * blockDim.x + threadIdx.x; i < n4; i += stride) {
        int c = (int)((i * 4) % D);
        float4 v = h4[i];
        v.x = v.x * s_scale[c]     + s_shift[c];
        v.y = v.y * s_scale[c + 1] + s_shift[c + 1];
        v.z = v.z * s_scale[c + 2] + s_shift[c + 2];
        v.w = v.w * s_scale[c + 3] + s_shift[c + 3];
        h4[i] = v;
    }
}

// ---------------- launch ----------------
extern "C" void kernel_launch(void* const* d_in, const int* in_sizes, int n_in,
                              void* d_out, int out_size) {
    const float* x        = (const float*)d_in[0];
    const float* rel      = (const float*)d_in[1];
    const float* enorm    = (const float*)d_in[2];
    const float* in_w     = (const float*)d_in[3];
    const float* out_w    = (const float*)d_in[4];
    const float* loop_w   = (const float*)d_in[5];
    const float* loop_rel = (const float*)d_in[6];
    const float* w_rel    = (const float*)d_in[7];
    const float* gamma    = (const float*)d_in[8];
    const float* beta     = (const float*)d_in[9];
    const int*   esrc     = (const int*)d_in[10];
    const int*   edst     = (const int*)d_in[11];
    const int*   etyp     = (const int*)d_in[12];

    float* h      = (float*)d_out;
    float* relout = h + (size_t)N_NODES * D;

    int E = in_sizes[2];           // 400000
    int half = E / 2;

    cudaFuncSetAttribute(k_gemm, cudaFuncAttributeMaxDynamicSharedMemorySize, SMEM_DYN);

    k_zero<<<2048, 256>>>();
    k_scatter<<<(E + 7) / 8, 256>>>(x, rel, enorm, esrc, edst, etyp, E, half);
    k_prep_rel<<<400, 624>>>(in_w, out_w, loop_w, loop_rel, rel, w_rel, relout);
    k_gemm<<<N_TILES, 512, SMEM_DYN>>>(x, h);
    k_norm<<<1024, 256>>>(h, gamma, beta);
    k_rel: ;
}

// round 16
// speedup vs baseline: 1.7576x; 1.7576x over previous
#include <cuda_runtime.h>
#include <cuda_bf16.h>
#include <cstdint>

#define N_NODES 100000
#define N_RELS  200
#define D       200
#define BN_EPS  1e-5f

#define SEGW 224          // per-segment padded K (200 real + 24 zero)
#define KCAT 672          // 3 * SEGW
#define NCHUNK 21         // 21 chunks of K=32 (7 per segment)
#define NPAD 224          // padded N for the GEMM (200 real)
#define N_TILES 782       // ceil(100000/128)

// ---------------- scratch (no cudaMalloc allowed) ----------------
__device__ float g_A[2][(size_t)N_NODES * D];   // in / out edge accumulators
__device__ float g_sum[D];
__device__ float g_sq[D];
__device__ __nv_bfloat16 g_Bhi[200 * KCAT];     // weights, split-bf16, K-major [n][kcat]
__device__ __nv_bfloat16 g_Blo[200 * KCAT];

// ---------------- PTX helpers (base ISA only — no sm_103a features!) ----------------
__device__ __forceinline__ uint32_t smem_u32(const void* p) {
    uint32_t a;
    asm("{ .reg .u64 t; cvta.to.shared.u64 t, %1; cvt.u32.u64 %0, t; }" : "=r"(a) : "l"(p));
    return a;
}

#define LDSM4(r, addr) \
    asm volatile("ldmatrix.sync.aligned.m8n8.x4.shared.b16 {%0,%1,%2,%3}, [%4];" \
                 : "=r"((r)[0]), "=r"((r)[1]), "=r"((r)[2]), "=r"((r)[3]) : "r"(addr))
#define LDSM2(r, addr) \
    asm volatile("ldmatrix.sync.aligned.m8n8.x2.shared.b16 {%0,%1}, [%2];" \
                 : "=r"((r)[0]), "=r"((r)[1]) : "r"(addr))

#define MMA16816(d, a, b0, b1) \
    asm volatile("mma.sync.aligned.m16n8k16.row.col.f32.bf16.bf16.f32 " \
                 "{%0,%1,%2,%3}, {%4,%5,%6,%7}, {%8,%9}, {%0,%1,%2,%3};" \
                 : "+f"((d)[0]), "+f"((d)[1]), "+f"((d)[2]), "+f"((d)[3]) \
                 : "r"((a)[0]), "r"((a)[1]), "r"((a)[2]), "r"((a)[3]), "r"(b0), "r"(b1))

#define REDV4(p, a, b, c, dd) \
    asm volatile("red.global.add.v4.f32 [%0], {%1,%2,%3,%4};" \
                 :: "l"(p), "f"(a), "f"(b), "f"(c), "f"(dd) : "memory")

// ---------------- zero scratch ----------------
__global__ void k_zero() {
    float4* p = (float4*)&g_A[0][0];
    size_t n4 = (size_t)2 * N_NODES * D / 4;
    size_t stride = (size_t)gridDim.x * blockDim.x;
    for (size_t i = (size_t)blockIdx.x * blockDim.x + threadIdx.x; i < n4; i += stride)
        p[i] = make_float4(0.f, 0.f, 0.f, 0.f);
    if (blockIdx.x == 0 && threadIdx.x < D) {
        g_sum[threadIdx.x] = 0.f;
        g_sq[threadIdx.x]  = 0.f;
    }
}

// ---------------- edge scatter: vector red.global.add.v4 ----------------
__global__ void k_scatter(const float* __restrict__ x,
                          const float* __restrict__ rel,
                          const float* __restrict__ enorm,
                          const int*  __restrict__ esrc,
                          const int*  __restrict__ edst,
                          const int*  __restrict__ etyp,
                          int E, int half) {
    int w    = (blockIdx.x * blockDim.x + threadIdx.x) >> 5;
    int lane = threadIdx.x & 31;
    if (w >= E) return;
    int s = esrc[w];
    int d = edst[w];
    int t = etyp[w];
    float c = enorm[w] * (1.f / 3.f);
    const float4* xr = (const float4*)(x   + (size_t)s * D);
    const float4* rr = (const float4*)(rel + (size_t)t * D);
    float* a = (w < half ? g_A[0] : g_A[1]) + (size_t)d * D;
    #pragma unroll
    for (int i = lane; i < D / 4; i += 32) {
        float4 xv = xr[i];
        float4 rv = rr[i];
        REDV4(a + 4 * i, xv.x * rv.x * c, xv.y * rv.y * c,
                          xv.z * rv.z * c, xv.w * rv.w * c);
    }
}

// ---------------- fused: weight prep (blocks 0..199) + rel_out GEMM (blocks 200..399) ----------------
__global__ void k_prep_rel(const float* __restrict__ in_w,
                           const float* __restrict__ out_w,
                           const float* __restrict__ loop_w,
                           const float* __restrict__ loop_rel,
                           const float* __restrict__ rel,
                           const float* __restrict__ w_rel,
                           float* __restrict__ relout) {
    if (blockIdx.x < 200) {
        int n    = blockIdx.x;       // 0..199
        int kcat = threadIdx.x;      // 0..671
        int seg  = kcat / SEGW;
        int k    = kcat - seg * SEGW;
        float v = 0.f;
        if (k < D) {
            const float* W = (seg == 0) ? in_w : (seg == 1) ? out_w : loop_w;
            v = W[k * D + n];
            if (seg == 2) v *= loop_rel[k] * (1.f / 3.f);
        }
        __nv_bfloat16 hi = __float2bfloat16(v);
        float lo = v - __bfloat162float(hi);
        g_Bhi[n * KCAT + kcat] = hi;
        g_Blo[n * KCAT + kcat] = __float2bfloat16(lo);
    } else {
        int i = blockIdx.x - 200;    // rel row
        int j = threadIdx.x;         // col
        if (j < D) {
            float s = 0.f;
            #pragma unroll 4
            for (int k = 0; k < D; k++)
                s = fmaf(rel[i * D + k], w_rel[k * D + j], s);
            relout[i * D + j] = s;
        }
    }
}

// ---------------- node GEMM on HMMA: K=32 chunks, double-buffered, fused BN stats ----------------
// h[128 x 200] = [A_in | A_out | x] @ Bsplit   per CTA tile.
// 512 threads = 16 warps in 4x4 grid; warp tile 32 rows x 56 cols (2 m16 x 7 n8).
#define A_STRIDE 80       // bytes per A row (32 bf16 = 64B padded to 80)
#define B_STRIDE 80
#define A_HI_OFF 0
#define A_LO_OFF 10240    // 128*80
#define B_HI_OFF 20480
#define B_LO_OFF 38400    // 20480 + 224*80
#define BUF_SZ   56320    // 38400 + 224*80
#define STAT_OFF (2 * BUF_SZ)                 // s_sum[200], s_sq[200]
#define SMEM_DYN (2 * BUF_SZ + 2 * 200 * 4)   // 114240

__global__ __launch_bounds__(512, 1)
void k_gemm(const float* __restrict__ x, float* __restrict__ h) {
    extern __shared__ __align__(16) char smem[];
    const int tid  = threadIdx.x;
    const int wid  = tid >> 5;
    const int lane = tid & 31;
    const int wr   = wid >> 2;          // warp row group 0..3
    const int wc   = wid & 3;           // warp col group 0..3
    const int row0 = blockIdx.x * 128;

    const uint32_t uBase = smem_u32(smem);
    float* s_sum = (float*)(smem + STAT_OFF);
    float* s_sq  = s_sum + 200;
    if (tid < 200) { s_sum[tid] = 0.f; s_sq[tid] = 0.f; }

    // ldmatrix lane offsets (add kk*32 for the second K-16 half)
    const uint32_t aOff = (uint32_t)(lane & 15) * A_STRIDE + (uint32_t)(lane >> 4) * 16;
    const uint32_t bOff4 = ((uint32_t)(((lane >> 4) << 3) + (lane & 7))) * B_STRIDE +
                           (uint32_t)((lane >> 3) & 1) * 16;
    const uint32_t bOff2 = (uint32_t)(lane & 7) * B_STRIDE + (uint32_t)((lane >> 3) & 1) * 16;

    const float* Asrc[3] = { g_A[0], g_A[1], x };

    float acc[2][7][4];
    #pragma unroll
    for (int m = 0; m < 2; m++)
        #pragma unroll
        for (int n = 0; n < 7; n++)
            #pragma unroll
            for (int q = 0; q < 4; q++) acc[m][n][q] = 0.f;

    // -------- prefetch state --------
    // A: 128 rows x 8 float4-groups = 1024 tasks -> thread does t, t+512
    //    task: row = t>>3, kg = t&7
    // B: 2 planes x 224 rows x 4 uint4-groups = 1792 tasks -> t, t+512, t+1024, (t+1536 if tid<256)
    float4 a_pf[2];
    uint4  b_pf[4];

    auto prefetch = [&](int seg, int kb) {
        const float* Ap = Asrc[seg];
        #pragma unroll
        for (int l = 0; l < 2; l++) {
            int task = tid + l * 512;
            int row = task >> 3, kg = task & 7;
            int col = kb + kg * 4;
            bool av = (row0 + row < N_NODES) && (col < D);
            a_pf[l] = av ? *(const float4*)(Ap + (size_t)(row0 + row) * D + col)
                         : make_float4(0.f, 0.f, 0.f, 0.f);
        }
        int kcat = seg * SEGW + kb;
        #pragma unroll
        for (int l = 0; l < 4; l++) {
            int task = tid + l * 512;
            if (l == 3 && tid >= 256) break;
            int pl = task / 896, rem = task - pl * 896, rw = rem >> 2, hf = rem & 3;
            const __nv_bfloat16* src = pl ? g_Blo : g_Bhi;
            b_pf[l] = (rw < 200) ? *(const uint4*)(src + rw * KCAT + kcat + hf * 8)
                                 : make_uint4(0, 0, 0, 0);
        }
    };

    auto store = [&](int buf) {
        char* base = smem + buf * BUF_SZ;
        #pragma unroll
        for (int l = 0; l < 2; l++) {
            int task = tid + l * 512;
            int row = task >> 3, kg = task & 7;
            float4 v = a_pf[l];
            __nv_bfloat16 h0 = __float2bfloat16(v.x);
            __nv_bfloat16 h1 = __float2bfloat16(v.y);
            __nv_bfloat16 h2 = __float2bfloat16(v.z);
            __nv_bfloat16 h3 = __float2bfloat16(v.w);
            __nv_bfloat16 l0 = __float2bfloat16(v.x - __bfloat162float(h0));
            __nv_bfloat16 l1 = __float2bfloat16(v.y - __bfloat162float(h1));
            __nv_bfloat16 l2 = __float2bfloat16(v.z - __bfloat162float(h2));
            __nv_bfloat16 l3 = __float2bfloat16(v.w - __bfloat162float(h3));
            uint32_t hij = (uint32_t)__bfloat16_as_ushort(h0) | ((uint32_t)__bfloat16_as_ushort(h1) << 16);
            uint32_t hkl = (uint32_t)__bfloat16_as_ushort(h2) | ((uint32_t)__bfloat16_as_ushort(h3) << 16);
            uint32_t lij = (uint32_t)__bfloat16_as_ushort(l0) | ((uint32_t)__bfloat16_as_ushort(l1) << 16);
            uint32_t lkl = (uint32_t)__bfloat16_as_ushort(l2) | ((uint32_t)__bfloat16_as_ushort(l3) << 16);
            *(uint2*)(base + A_HI_OFF + row * A_STRIDE + kg * 8) = make_uint2(hij, hkl);
            *(uint2*)(base + A_LO_OFF + row * A_STRIDE + kg * 8) = make_uint2(lij, lkl);
        }
        #pragma unroll
        for (int l = 0; l < 4; l++) {
            int task = tid + l * 512;
            if (l == 3 && tid >= 256) break;
            int pl = task / 896, rem = task - pl * 896, rw = rem >> 2, hf = rem & 3;
            char* dst = base + (pl ? B_LO_OFF : B_HI_OFF);
            *(uint4*)(dst + rw * B_STRIDE + hf * 16) = b_pf[l];
        }
    };

    // ---- prologue ----
    prefetch(0, 0);
    store(0);
    __syncthreads();
    prefetch(0, 32);          // chunk 1 in flight

    int seg = 0, kb = 32;     // (seg,kb) of the chunk currently prefetched
    for (int c = 0; c < NCHUNK; c++) {
        const uint32_t buf = (uint32_t)(c & 1) * BUF_SZ;
        const uint32_t uAhi = uBase + buf + A_HI_OFF;
        const uint32_t uAlo = uBase + buf + A_LO_OFF;
        const uint32_t uBhi = uBase + buf + B_HI_OFF;
        const uint32_t uBlo = uBase + buf + B_LO_OFF;

        // ---- compute chunk c: two K-16 halves ----
        #pragma unroll
        for (int kk = 0; kk < 2; kk++) {
            const uint32_t ksh = (uint32_t)kk * 32;
            uint32_t ah[2][4], al[2][4];
            #pragma unroll
            for (int mt = 0; mt < 2; mt++) {
                uint32_t rbase = (uint32_t)(wr * 32 + mt * 16) * A_STRIDE + ksh;
                LDSM4(ah[mt], uAhi + rbase + aOff);
                LDSM4(al[mt], uAlo + rbase + aOff);
            }
            #pragma unroll
            for (int np = 0; np < 3; np++) {
                uint32_t nbase = (uint32_t)(wc * 56 + np * 16) * B_STRIDE + ksh;
                uint32_t bh[4], bl[4];
                LDSM4(bh, uBhi + nbase + bOff4);
                LDSM4(bl, uBlo + nbase + bOff4);
                #pragma unroll
                for (int mt = 0; mt < 2; mt++) {
                    MMA16816(acc[mt][2 * np],     ah[mt], bh[0], bh[1]);
                    MMA16816(acc[mt][2 * np],     ah[mt], bl[0], bl[1]);
                    MMA16816(acc[mt][2 * np],     al[mt], bh[0], bh[1]);
                    MMA16816(acc[mt][2 * np + 1], ah[mt], bh[2], bh[3]);
                    MMA16816(acc[mt][2 * np + 1], ah[mt], bl[2], bl[3]);
                    MMA16816(acc[mt][2 * np + 1], al[mt], bh[2], bh[3]);
                }
            }
            {
                uint32_t nbase = (uint32_t)(wc * 56 + 48) * B_STRIDE + ksh;
                uint32_t bh[2], bl[2];
                LDSM2(bh, uBhi + nbase + bOff2);
                LDSM2(bl, uBlo + nbase + bOff2);
                #pragma unroll
                for (int mt = 0; mt < 2; mt++) {
                    MMA16816(acc[mt][6], ah[mt], bh[0], bh[1]);
                    MMA16816(acc[mt][6], ah[mt], bl[0], bl[1]);
                    MMA16816(acc[mt][6], al[mt], bh[0], bh[1]);
                }
            }
        }

        // ---- store prefetched chunk c+1 into alternate buffer, start LDG c+2 ----
        if (c + 1 < NCHUNK) {
            store((c + 1) & 1);
            kb += 32;
            if (kb == SEGW) { kb = 0; seg++; }
            if (c + 2 < NCHUNK) prefetch(seg, kb);
        }
        __syncthreads();
    }

    // ---- epilogue 1: write h ----
    #pragma unroll
    for (int mt = 0; mt < 2; mt++) {
        int rlo = row0 + wr * 32 + mt * 16 + (lane >> 2);
        int rhi = rlo + 8;
        #pragma unroll
        for (int nt = 0; nt < 7; nt++) {
            int col = wc * 56 + nt * 8 + 2 * (lane & 3);
            if (col < D) {
                if (rlo < N_NODES)
                    *(float2*)(h + (size_t)rlo * D + col) = make_float2(acc[mt][nt][0], acc[mt][nt][1]);
                if (rhi < N_NODES)
                    *(float2*)(h + (size_t)rhi * D + col) = make_float2(acc[mt][nt][2], acc[mt][nt][3]);
            }
        }
    }

    // ---- epilogue 2: fused BN stats (sum / sumsq per column) ----
    #pragma unroll
    for (int nt = 0; nt < 7; nt++) {
        float s0 = acc[0][nt][0] + acc[0][nt][2] + acc[1][nt][0] + acc[1][nt][2];
        float s1 = acc[0][nt][1] + acc[0][nt][3] + acc[1][nt][1] + acc[1][nt][3];
        float q0 = acc[0][nt][0]*acc[0][nt][0] + acc[0][nt][2]*acc[0][nt][2]
                 + acc[1][nt][0]*acc[1][nt][0] + acc[1][nt][2]*acc[1][nt][2];
        float q1 = acc[0][nt][1]*acc[0][nt][1] + acc[0][nt][3]*acc[0][nt][3]
                 + acc[1][nt][1]*acc[1][nt][1] + acc[1][nt][3]*acc[1][nt][3];
        #pragma unroll
        for (int m = 4; m <= 16; m <<= 1) {
            s0 += __shfl_xor_sync(0xffffffffu, s0, m);
            s1 += __shfl_xor_sync(0xffffffffu, s1, m);
            q0 += __shfl_xor_sync(0xffffffffu, q0, m);
            q1 += __shfl_xor_sync(0xffffffffu, q1, m);
        }
        if (lane < 4) {
            int col = wc * 56 + nt * 8 + 2 * lane;
            if (col < D) {
                atomicAdd(&s_sum[col],     s0);
                atomicAdd(&s_sq[col],      q0);
                atomicAdd(&s_sum[col + 1], s1);
                atomicAdd(&s_sq[col + 1],  q1);
            }
        }
    }
    __syncthreads();
    if (tid < D) {
        atomicAdd(&g_sum[tid], s_sum[tid]);
        atomicAdd(&g_sq[tid],  s_sq[tid]);
    }
}

// ---------------- BatchNorm normalize (in place, float4) ----------------
__global__ void k_norm(float* __restrict__ h,
                       const float* __restrict__ gamma,
                       const float* __restrict__ beta) {
    __shared__ float s_scale[D];
    __shared__ float s_shift[D];
    if (threadIdx.x < D) {
        const float invN = 1.f / (float)N_NODES;
        float mean = g_sum[threadIdx.x] * invN;
        float var  = g_sq[threadIdx.x] * invN - mean * mean;
        float inv  = rsqrtf(var + BN_EPS);
        float sc   = inv * gamma[threadIdx.x];
        s_scale[threadIdx.x] = sc;
        s_shift[threadIdx.x] = beta[threadIdx.x] - mean * sc;
    }
    __syncthreads();
    float4* h4 = (float4*)h;
    size_t n4 = (size_t)N_NODES * D / 4;
    size_t stride = (size_t)gridDim.x * blockDim.x;
    for (size_t i = (size_t)blockIdx.x * blockDim.x + threadIdx.x; i < n4; i += stride) {
        int c = (int)((i * 4) % D);
        float4 v = h4[i];
        v.x = v.x * s_scale[c]     + s_shift[c];
        v.y = v.y * s_scale[c + 1] + s_shift[c + 1];
        v.z = v.z * s_scale[c + 2] + s_shift[c + 2];
        v.w = v.w * s_scale[c + 3] + s_shift[c + 3];
        h4[i] = v;
    }
}

// ---------------- launch ----------------
extern "C" void kernel_launch(void* const* d_in, const int* in_sizes, int n_in,
                              void* d_out, int out_size) {
    const float* x        = (const float*)d_in[0];
    const float* rel      = (const float*)d_in[1];
    const float* enorm    = (const float*)d_in[2];
    const float* in_w     = (const float*)d_in[3];
    const float* out_w    = (const float*)d_in[4];
    const float* loop_w   = (const float*)d_in[5];
    const float* loop_rel = (const float*)d_in[6];
    const float* w_rel    = (const float*)d_in[7];
    const float* gamma    = (const float*)d_in[8];
    const float* beta     = (const float*)d_in[9];
    const int*   esrc     = (const int*)d_in[10];
    const int*   edst     = (const int*)d_in[11];
    const int*   etyp     = (const int*)d_in[12];

    float* h      = (float*)d_out;
    float* relout = h + (size_t)N_NODES * D;

    int E = in_sizes[2];           // 400000
    int half = E / 2;

    cudaFuncSetAttribute(k_gemm, cudaFuncAttributeMaxDynamicSharedMemorySize, SMEM_DYN);

    k_zero<<<2048, 256>>>();
    k_scatter<<<(E + 7) / 8, 256>>>(x, rel, enorm, esrc, edst, etyp, E, half);
    k_prep_rel<<<400, 672>>>(in_w, out_w, loop_w, loop_rel, rel, w_rel, relout);
    k_gemm<<<N_TILES, 512, SMEM_DYN>>>(x, h);
    k_norm<<<1024, 256>>>(h, gamma, beta);
}

// round 17
// speedup vs baseline: 1.8402x; 1.0470x over previous
#include <cuda_runtime.h>
#include <cuda_bf16.h>
#include <cstdint>

#define N_NODES 100000
#define N_RELS  200
#define D       200
#define BN_EPS  1e-5f

#define SEGW 208          // per-segment padded K (200 real + 8 zero)
#define KCAT 624          // 3 * SEGW
#define NCHUNK 39         // 39 chunks of K=16
#define NPAD 224          // padded N for the GEMM (200 real)
#define N_TILES 782       // ceil(100000/128)

// ---------------- scratch (no cudaMalloc allowed) ----------------
__device__ float g_A[2][(size_t)N_NODES * D];   // in / out edge accumulators
__device__ float g_sum[D];
__device__ float g_sq[D];
__device__ __nv_bfloat16 g_Bhi[200 * KCAT];     // weights, split-bf16, K-major [n][kcat]
__device__ __nv_bfloat16 g_Blo[200 * KCAT];

// ---------------- PTX helpers (base ISA only — no sm_103a features!) ----------------
__device__ __forceinline__ uint32_t smem_u32(const void* p) {
    uint32_t a;
    asm("{ .reg .u64 t; cvta.to.shared.u64 t, %1; cvt.u32.u64 %0, t; }" : "=r"(a) : "l"(p));
    return a;
}

#define LDSM4(r, addr) \
    asm volatile("ldmatrix.sync.aligned.m8n8.x4.shared.b16 {%0,%1,%2,%3}, [%4];" \
                 : "=r"((r)[0]), "=r"((r)[1]), "=r"((r)[2]), "=r"((r)[3]) : "r"(addr))
#define LDSM2(r, addr) \
    asm volatile("ldmatrix.sync.aligned.m8n8.x2.shared.b16 {%0,%1}, [%2];" \
                 : "=r"((r)[0]), "=r"((r)[1]) : "r"(addr))

#define MMA16816(d, a, b0, b1) \
    asm volatile("mma.sync.aligned.m16n8k16.row.col.f32.bf16.bf16.f32 " \
                 "{%0,%1,%2,%3}, {%4,%5,%6,%7}, {%8,%9}, {%0,%1,%2,%3};" \
                 : "+f"((d)[0]), "+f"((d)[1]), "+f"((d)[2]), "+f"((d)[3]) \
                 : "r"((a)[0]), "r"((a)[1]), "r"((a)[2]), "r"((a)[3]), "r"(b0), "r"(b1))

#define REDV4(p, a, b, c, dd) \
    asm volatile("red.global.add.v4.f32 [%0], {%1,%2,%3,%4};" \
                 :: "l"(p), "f"(a), "f"(b), "f"(c), "f"(dd) : "memory")

// ---------------- zero scratch ----------------
__global__ void k_zero() {
    float4* p = (float4*)&g_A[0][0];
    size_t n4 = (size_t)2 * N_NODES * D / 4;
    size_t stride = (size_t)gridDim.x * blockDim.x;
    for (size_t i = (size_t)blockIdx.x * blockDim.x + threadIdx.x; i < n4; i += stride)
        p[i] = make_float4(0.f, 0.f, 0.f, 0.f);
    if (blockIdx.x == 0 && threadIdx.x < D) {
        g_sum[threadIdx.x] = 0.f;
        g_sq[threadIdx.x]  = 0.f;
    }
}

// ---------------- edge scatter: vector red.global.add.v4 ----------------
__global__ void k_scatter(const float* __restrict__ x,
                          const float* __restrict__ rel,
                          const float* __restrict__ enorm,
                          const int*  __restrict__ esrc,
                          const int*  __restrict__ edst,
                          const int*  __restrict__ etyp,
                          int E, int half) {
    int w    = (blockIdx.x * blockDim.x + threadIdx.x) >> 5;
    int lane = threadIdx.x & 31;
    if (w >= E) return;
    int s = esrc[w];
    int d = edst[w];
    int t = etyp[w];
    float c = enorm[w] * (1.f / 3.f);
    const float4* xr = (const float4*)(x   + (size_t)s * D);
    const float4* rr = (const float4*)(rel + (size_t)t * D);
    float* a = (w < half ? g_A[0] : g_A[1]) + (size_t)d * D;
    #pragma unroll
    for (int i = lane; i < D / 4; i += 32) {
        float4 xv = xr[i];
        float4 rv = rr[i];
        REDV4(a + 4 * i, xv.x * rv.x * c, xv.y * rv.y * c,
                          xv.z * rv.z * c, xv.w * rv.w * c);
    }
}

// ---------------- fused: weight prep (blocks 0..199) + rel_out GEMM (blocks 200..399) ----------------
__global__ void k_prep_rel(const float* __restrict__ in_w,
                           const float* __restrict__ out_w,
                           const float* __restrict__ loop_w,
                           const float* __restrict__ loop_rel,
                           const float* __restrict__ rel,
                           const float* __restrict__ w_rel,
                           float* __restrict__ relout) {
    if (blockIdx.x < 200) {
        int n    = blockIdx.x;       // 0..199
        int kcat = threadIdx.x;      // 0..623
        int seg  = kcat / SEGW;
        int k    = kcat - seg * SEGW;
        float v = 0.f;
        if (k < D) {
            const float* W = (seg == 0) ? in_w : (seg == 1) ? out_w : loop_w;
            v = W[k * D + n];
            if (seg == 2) v *= loop_rel[k] * (1.f / 3.f);
        }
        __nv_bfloat16 hi = __float2bfloat16(v);
        float lo = v - __bfloat162float(hi);
        g_Bhi[n * KCAT + kcat] = hi;
        g_Blo[n * KCAT + kcat] = __float2bfloat16(lo);
    } else {
        int i = blockIdx.x - 200;    // rel row
        int j = threadIdx.x;         // col
        if (j < D) {
            float s = 0.f;
            #pragma unroll 4
            for (int k = 0; k < D; k++)
                s = fmaf(rel[i * D + k], w_rel[k * D + j], s);
            relout[i * D + j] = s;
        }
    }
}

// ---------------- node GEMM on HMMA: K=16 double-buffer, chain-broken MMA order ----------------
// h[128 x 200] = [A_in | A_out | x] @ Bsplit   per CTA tile.
// 512 threads = 16 warps in 4x4 grid; warp tile 32 rows x 56 cols (2 m16 x 7 n8).
#define A_STRIDE 48       // bytes per A row (16 bf16 padded to 24)
#define B_STRIDE 48
#define A_HI_OFF 0
#define A_LO_OFF 6144     // 128*48
#define B_HI_OFF 12288
#define B_LO_OFF 23040    // 12288 + 224*48
#define BUF_SZ   33792    // 23040 + 224*48
#define STAT_OFF (2 * BUF_SZ)          // s_sum[200], s_sq[200]
#define SMEM_DYN (2 * BUF_SZ + 2 * 200 * 4)   // 69184

__global__ __launch_bounds__(512, 1)
void k_gemm(const float* __restrict__ x, float* __restrict__ h) {
    extern __shared__ __align__(16) char smem[];
    const int tid  = threadIdx.x;
    const int wid  = tid >> 5;
    const int lane = tid & 31;
    const int wr   = wid >> 2;          // warp row group 0..3
    const int wc   = wid & 3;           // warp col group 0..3
    const int row0 = blockIdx.x * 128;

    const uint32_t uBase = smem_u32(smem);
    float* s_sum = (float*)(smem + STAT_OFF);
    float* s_sq  = s_sum + 200;
    if (tid < 200) { s_sum[tid] = 0.f; s_sq[tid] = 0.f; }

    // ldmatrix lane offsets
    const uint32_t aOff = (uint32_t)(lane & 15) * A_STRIDE + (uint32_t)(lane >> 4) * 16;
    const uint32_t bOff4 = ((uint32_t)(((lane >> 4) << 3) + (lane & 7))) * B_STRIDE +
                           (uint32_t)((lane >> 3) & 1) * 16;
    const uint32_t bOff2 = (uint32_t)(lane & 7) * B_STRIDE + (uint32_t)((lane >> 3) & 1) * 16;

    const float* Asrc[3] = { g_A[0], g_A[1], x };

    float acc[2][7][4];
    #pragma unroll
    for (int m = 0; m < 2; m++)
        #pragma unroll
        for (int n = 0; n < 7; n++)
            #pragma unroll
            for (int q = 0; q < 4; q++) acc[m][n][q] = 0.f;

    // prefetch task mapping
    const int prow = tid >> 2;          // A row
    const int pkg  = tid & 3;           // A k-group (4 floats)
    float4 a_pf;
    uint4  b_pf0, b_pf1;

    auto prefetch = [&](int seg, int kb) {
        const float* Ap = Asrc[seg];
        bool av = (row0 + prow < N_NODES) && (kb + pkg * 4 < D);
        a_pf = av ? *(const float4*)(Ap + (size_t)(row0 + prow) * D + kb + pkg * 4)
                  : make_float4(0.f, 0.f, 0.f, 0.f);
        int kcat = seg * SEGW + kb;
        {
            int t0 = tid;
            int pl = t0 / 448, rem = t0 - pl * 448, rw = rem >> 1, hf = rem & 1;
            const __nv_bfloat16* src = pl ? g_Blo : g_Bhi;
            b_pf0 = (rw < 200) ? *(const uint4*)(src + rw * KCAT + kcat + hf * 8)
                               : make_uint4(0, 0, 0, 0);
        }
        if (tid < 384) {
            int t1 = tid + 512;
            int pl = t1 / 448, rem = t1 - pl * 448, rw = rem >> 1, hf = rem & 1;
            const __nv_bfloat16* src = pl ? g_Blo : g_Bhi;
            b_pf1 = (rw < 200) ? *(const uint4*)(src + rw * KCAT + kcat + hf * 8)
                               : make_uint4(0, 0, 0, 0);
        }
    };

    auto store = [&](int buf) {
        char* base = smem + buf * BUF_SZ;
        __nv_bfloat16 h0 = __float2bfloat16(a_pf.x);
        __nv_bfloat16 h1 = __float2bfloat16(a_pf.y);
        __nv_bfloat16 h2 = __float2bfloat16(a_pf.z);
        __nv_bfloat16 h3 = __float2bfloat16(a_pf.w);
        __nv_bfloat16 l0 = __float2bfloat16(a_pf.x - __bfloat162float(h0));
        __nv_bfloat16 l1 = __float2bfloat16(a_pf.y - __bfloat162float(h1));
        __nv_bfloat16 l2 = __float2bfloat16(a_pf.z - __bfloat162float(h2));
        __nv_bfloat16 l3 = __float2bfloat16(a_pf.w - __bfloat162float(h3));
        uint32_t hij = (uint32_t)__bfloat16_as_ushort(h0) | ((uint32_t)__bfloat16_as_ushort(h1) << 16);
        uint32_t hkl = (uint32_t)__bfloat16_as_ushort(h2) | ((uint32_t)__bfloat16_as_ushort(h3) << 16);
        uint32_t lij = (uint32_t)__bfloat16_as_ushort(l0) | ((uint32_t)__bfloat16_as_ushort(l1) << 16);
        uint32_t lkl = (uint32_t)__bfloat16_as_ushort(l2) | ((uint32_t)__bfloat16_as_ushort(l3) << 16);
        *(uint2*)(base + A_HI_OFF + prow * A_STRIDE + pkg * 8) = make_uint2(hij, hkl);
        *(uint2*)(base + A_LO_OFF + prow * A_STRIDE + pkg * 8) = make_uint2(lij, lkl);
        {
            int t0 = tid;
            int pl = t0 / 448, rem = t0 - pl * 448, rw = rem >> 1, hf = rem & 1;
            char* dst = base + (pl ? B_LO_OFF : B_HI_OFF);
            *(uint4*)(dst + rw * B_STRIDE + hf * 16) = b_pf0;
        }
        if (tid < 384) {
            int t1 = tid + 512;
            int pl = t1 / 448, rem = t1 - pl * 448, rw = rem >> 1, hf = rem & 1;
            char* dst = base + (pl ? B_LO_OFF : B_HI_OFF);
            *(uint4*)(dst + rw * B_STRIDE + hf * 16) = b_pf1;
        }
    };

    // ---- prologue ----
    prefetch(0, 0);
    store(0);
    __syncthreads();
    prefetch(0, 16);          // chunk 1 in flight

    int seg = 0, kb = 16;     // (seg,kb) of the chunk currently prefetched
    for (int c = 0; c < NCHUNK; c++) {
        const uint32_t buf = (uint32_t)(c & 1) * BUF_SZ;
        const uint32_t uAhi = uBase + buf + A_HI_OFF;
        const uint32_t uAlo = uBase + buf + A_LO_OFF;
        const uint32_t uBhi = uBase + buf + B_HI_OFF;
        const uint32_t uBlo = uBase + buf + B_LO_OFF;

        // ---- compute chunk c — term-pass order breaks accumulator RAW chains ----
        uint32_t ah[2][4], al[2][4];
        #pragma unroll
        for (int mt = 0; mt < 2; mt++) {
            uint32_t rbase = (uint32_t)(wr * 32 + mt * 16) * A_STRIDE;
            LDSM4(ah[mt], uAhi + rbase + aOff);
            LDSM4(al[mt], uAlo + rbase + aOff);
        }
        #pragma unroll
        for (int np = 0; np < 3; np++) {
            uint32_t nbase = (uint32_t)(wc * 56 + np * 16) * B_STRIDE;
            uint32_t bh[4], bl[4];
            LDSM4(bh, uBhi + nbase + bOff4);
            LDSM4(bl, uBlo + nbase + bOff4);
            // term hh — 4 distinct accumulators
            MMA16816(acc[0][2 * np],     ah[0], bh[0], bh[1]);
            MMA16816(acc[1][2 * np],     ah[1], bh[0], bh[1]);
            MMA16816(acc[0][2 * np + 1], ah[0], bh[2], bh[3]);
            MMA16816(acc[1][2 * np + 1], ah[1], bh[2], bh[3]);
            // term hl
            MMA16816(acc[0][2 * np],     ah[0], bl[0], bl[1]);
            MMA16816(acc[1][2 * np],     ah[1], bl[0], bl[1]);
            MMA16816(acc[0][2 * np + 1], ah[0], bl[2], bl[3]);
            MMA16816(acc[1][2 * np + 1], ah[1], bl[2], bl[3]);
            // term lh
            MMA16816(acc[0][2 * np],     al[0], bh[0], bh[1]);
            MMA16816(acc[1][2 * np],     al[1], bh[0], bh[1]);
            MMA16816(acc[0][2 * np + 1], al[0], bh[2], bh[3]);
            MMA16816(acc[1][2 * np + 1], al[1], bh[2], bh[3]);
        }
        {   // tail n-tile 6 — distance-2 ordering
            uint32_t nbase = (uint32_t)(wc * 56 + 48) * B_STRIDE;
            uint32_t bh[2], bl[2];
            LDSM2(bh, uBhi + nbase + bOff2);
            LDSM2(bl, uBlo + nbase + bOff2);
            MMA16816(acc[0][6], ah[0], bh[0], bh[1]);
            MMA16816(acc[1][6], ah[1], bh[0], bh[1]);
            MMA16816(acc[0][6], ah[0], bl[0], bl[1]);
            MMA16816(acc[1][6], ah[1], bl[0], bl[1]);
            MMA16816(acc[0][6], al[0], bh[0], bh[1]);
            MMA16816(acc[1][6], al[1], bh[0], bh[1]);
        }

        // ---- store prefetched chunk c+1 into alternate buffer, start LDG c+2 ----
        if (c + 1 < NCHUNK) {
            store((c + 1) & 1);
            kb += 16;
            if (kb == SEGW) { kb = 0; seg++; }
            if (c + 2 < NCHUNK) prefetch(seg, kb);
        }
        __syncthreads();
    }

    // ---- epilogue 1: write h ----
    #pragma unroll
    for (int mt = 0; mt < 2; mt++) {
        int rlo = row0 + wr * 32 + mt * 16 + (lane >> 2);
        int rhi = rlo + 8;
        #pragma unroll
        for (int nt = 0; nt < 7; nt++) {
            int col = wc * 56 + nt * 8 + 2 * (lane & 3);
            if (col < D) {
                if (rlo < N_NODES)
                    *(float2*)(h + (size_t)rlo * D + col) = make_float2(acc[mt][nt][0], acc[mt][nt][1]);
                if (rhi < N_NODES)
                    *(float2*)(h + (size_t)rhi * D + col) = make_float2(acc[mt][nt][2], acc[mt][nt][3]);
            }
        }
    }

    // ---- epilogue 2: fused BN stats (sum / sumsq per column) ----
    #pragma unroll
    for (int nt = 0; nt < 7; nt++) {
        float s0 = acc[0][nt][0] + acc[0][nt][2] + acc[1][nt][0] + acc[1][nt][2];
        float s1 = acc[0][nt][1] + acc[0][nt][3] + acc[1][nt][1] + acc[1][nt][3];
        float q0 = acc[0][nt][0]*acc[0][nt][0] + acc[0][nt][2]*acc[0][nt][2]
                 + acc[1][nt][0]*acc[1][nt][0] + acc[1][nt][2]*acc[1][nt][2];
        float q1 = acc[0][nt][1]*acc[0][nt][1] + acc[0][nt][3]*acc[0][nt][3]
                 + acc[1][nt][1]*acc[1][nt][1] + acc[1][nt][3]*acc[1][nt][3];
        #pragma unroll
        for (int m = 4; m <= 16; m <<= 1) {
            s0 += __shfl_xor_sync(0xffffffffu, s0, m);
            s1 += __shfl_xor_sync(0xffffffffu, s1, m);
            q0 += __shfl_xor_sync(0xffffffffu, q0, m);
            q1 += __shfl_xor_sync(0xffffffffu, q1, m);
        }
        if (lane < 4) {
            int col = wc * 56 + nt * 8 + 2 * lane;
            if (col < D) {
                atomicAdd(&s_sum[col],     s0);
                atomicAdd(&s_sq[col],      q0);
                atomicAdd(&s_sum[col + 1], s1);
                atomicAdd(&s_sq[col + 1],  q1);
            }
        }
    }
    __syncthreads();
    if (tid < D) {
        atomicAdd(&g_sum[tid], s_sum[tid]);
        atomicAdd(&g_sq[tid],  s_sq[tid]);
    }
}

// ---------------- BatchNorm normalize (in place, float4) ----------------
__global__ void k_norm(float* __restrict__ h,
                       const float* __restrict__ gamma,
                       const float* __restrict__ beta) {
    __shared__ float s_scale[D];
    __shared__ float s_shift[D];
    if (threadIdx.x < D) {
        const float invN = 1.f / (float)N_NODES;
        float mean = g_sum[threadIdx.x] * invN;
        float var  = g_sq[threadIdx.x] * invN - mean * mean;
        float inv  = rsqrtf(var + BN_EPS);
        float sc   = inv * gamma[threadIdx.x];
        s_scale[threadIdx.x] = sc;
        s_shift[threadIdx.x] = beta[threadIdx.x] - mean * sc;
    }
    __syncthreads();
    float4* h4 = (float4*)h;
    size_t n4 = (size_t)N_NODES * D / 4;
    size_t stride = (size_t)gridDim.x * blockDim.x;
    for (size_t i = (size_t)blockIdx.x * blockDim.x + threadIdx.x; i < n4; i += stride) {
        int c = (int)((i * 4) % D);
        float4 v = h4[i];
        v.x = v.x * s_scale[c]     + s_shift[c];
        v.y = v.y * s_scale[c + 1] + s_shift[c + 1];
        v.z = v.z * s_scale[c + 2] + s_shift[c + 2];
        v.w = v.w * s_scale[c + 3] + s_shift[c + 3];
        h4[i] = v;
    }
}

// ---------------- launch ----------------
extern "C" void kernel_launch(void* const* d_in, const int* in_sizes, int n_in,
                              void* d_out, int out_size) {
    const float* x        = (const float*)d_in[0];
    const float* rel      = (const float*)d_in[1];
    const float* enorm    = (const float*)d_in[2];
    const float* in_w     = (const float*)d_in[3];
    const float* out_w    = (const float*)d_in[4];
    const float* loop_w   = (const float*)d_in[5];
    const float* loop_rel = (const float*)d_in[6];
    const float* w_rel    = (const float*)d_in[7];
    const float* gamma    = (const float*)d_in[8];
    const float* beta     = (const float*)d_in[9];
    const int*   esrc     = (const int*)d_in[10];
    const int*   edst     = (const int*)d_in[11];
    const int*   etyp     = (const int*)d_in[12];

    float* h      = (float*)d_out;
    float* relout = h + (size_t)N_NODES * D;

    int E = in_sizes[2];           // 400000
    int half = E / 2;

    cudaFuncSetAttribute(k_gemm, cudaFuncAttributeMaxDynamicSharedMemorySize, SMEM_DYN);

    k_zero<<<2048, 256>>>();
    k_scatter<<<(E + 7) / 8, 256>>>(x, rel, enorm, esrc, edst, etyp, E, half);
    k_prep_rel<<<400, 624>>>(in_w, out_w, loop_w, loop_rel, rel, w_rel, relout);
    k_gemm<<<N_TILES, 512, SMEM_DYN>>>(x, h);
    k_norm<<<1024, 256>>>(h, gamma, beta);
}